// round 1
// baseline (speedup 1.0000x reference)
#include <cuda_runtime.h>
#include <cuda_bf16.h>
#include <math.h>

#define BB 32
#define SS 1024
#define HH 768
#define EE 128
#define WW 8
#define PP 512
#define NTT 5
#define NRR 9
#define DD1 128
#define HEADS1 2
#define DD2 64
#define RDD 32
#define F1 256  // HEADS1*DD1

// ---------------- scratch (device globals, no allocation) ----------------
static __device__ float g_x0[BB*EE*HH];          // pooled + type emb
static __device__ float g_h1[BB*EE*F1];          // x0 @ W1
static __device__ float g_s1[BB*HEADS1*EE];
static __device__ float g_d1[BB*HEADS1*EE];
static __device__ float g_alpha1[BB*HEADS1*EE*EE];
static __device__ float g_o1[BB*EE*F1];
static __device__ float g_x1[BB*EE*F1];
static __device__ float g_h2[BB*EE*DD2];
static __device__ float g_s2[BB*EE];
static __device__ float g_d2[BB*EE];
static __device__ float g_alpha2[BB*EE*EE];
static __device__ float g_o2[BB*EE*DD2];
static __device__ float g_x2[BB*EE*DD2];
static __device__ float g_p1[BB*EE*256];
static __device__ float g_p2[BB*EE*256];
static __device__ float g_cls[BB*256];
static __device__ float g_rel[NRR*256];

// ---------------- 1. entity pooling + type embedding ----------------
__global__ void pool_kernel(const float* __restrict__ seq,
                            const int* __restrict__ starts,
                            const int* __restrict__ type_ids,
                            const float* __restrict__ temb,
                            float* __restrict__ x0) {
    int be = blockIdx.x;                 // b*EE + e
    int b = be >> 7;
    int t = threadIdx.x;                 // 256 threads
    __shared__ float toks[WW*HH];        // 24 KB
    __shared__ float colsum[HH];
    __shared__ float logits[WW];

    int start = starts[be];
    const float* base = seq + ((size_t)b*SS + start)*HH;
    // contiguous 8*768 block
    for (int i = t; i < WW*HH; i += 256) toks[i] = base[i];
    __syncthreads();

    for (int h = t; h < HH; h += 256) {
        float cs = 0.f;
        #pragma unroll
        for (int w = 0; w < WW; w++) cs += toks[w*HH + h];
        colsum[h] = cs;
    }
    __syncthreads();

    int warp = t >> 5, lane = t & 31;
    {   // warp w computes logit w = dot(toks[w], mean) ; mean = colsum/8
        float acc = 0.f;
        for (int h = lane; h < HH; h += 32) acc += toks[warp*HH + h] * colsum[h];
        #pragma unroll
        for (int off = 16; off > 0; off >>= 1) acc += __shfl_xor_sync(0xffffffffu, acc, off);
        if (lane == 0) logits[warp] = acc * 0.125f;
    }
    __syncthreads();

    float m = logits[0];
    #pragma unroll
    for (int w = 1; w < WW; w++) m = fmaxf(m, logits[w]);
    float ex[WW]; float sum = 0.f;
    #pragma unroll
    for (int w = 0; w < WW; w++) { ex[w] = __expf(logits[w] - m); sum += ex[w]; }
    float inv = 1.f / sum;

    int type = type_ids[be];
    const float* te = temb + (size_t)type*HH;
    for (int h = t; h < HH; h += 256) {
        float p = 0.f;
        #pragma unroll
        for (int w = 0; w < WW; w++) p += ex[w] * toks[w*HH + h];
        x0[(size_t)be*HH + h] = p*inv + te[h];
    }
}

// ---------------- generic batched tiled GEMM (fp32) ----------------
// C[M,N] = A[M,K] @ B[K,N]; all dims multiples of (64,64,16).
// batch: bz over gridDim.z; bb = bz/Hh, hh = bz%Hh.
__global__ void gemm_kernel(const float* __restrict__ A,
                            const float* __restrict__ Bm,
                            float* __restrict__ C,
                            int M, int N, int K, int lda, int ldb, int ldc,
                            int Hh, long sA, long sBb, long sBh, long sCb, long sCh) {
    int bz = blockIdx.z;
    int bb = bz / Hh, hh = bz - bb*Hh;
    A  += (long)bz * sA;
    Bm += (long)bb * sBb + (long)hh * sBh;
    C  += (long)bb * sCb + (long)hh * sCh;

    __shared__ float As[16][64];
    __shared__ float Bs[16][68];
    int tid = threadIdx.x;                 // 256
    int tx = tid & 15, ty = tid >> 4;
    int m0 = blockIdx.y * 64, n0 = blockIdx.x * 64;
    float acc[4][4] = {};

    int arow = tid >> 2, akq = (tid & 3) * 4;
    int brow = tid >> 4, bnq = (tid & 15) * 4;

    for (int k0 = 0; k0 < K; k0 += 16) {
        float4 av = *(const float4*)(A + (size_t)(m0 + arow)*lda + k0 + akq);
        As[akq+0][arow] = av.x; As[akq+1][arow] = av.y;
        As[akq+2][arow] = av.z; As[akq+3][arow] = av.w;
        float4 bv = *(const float4*)(Bm + (size_t)(k0 + brow)*ldb + n0 + bnq);
        Bs[brow][bnq+0] = bv.x; Bs[brow][bnq+1] = bv.y;
        Bs[brow][bnq+2] = bv.z; Bs[brow][bnq+3] = bv.w;
        __syncthreads();
        #pragma unroll
        for (int k = 0; k < 16; k++) {
            float ar[4], bc[4];
            #pragma unroll
            for (int r = 0; r < 4; r++) ar[r] = As[k][ty*4 + r];
            #pragma unroll
            for (int c = 0; c < 4; c++) bc[c] = Bs[k][tx*4 + c];
            #pragma unroll
            for (int r = 0; r < 4; r++)
                #pragma unroll
                for (int c = 0; c < 4; c++) acc[r][c] += ar[r]*bc[c];
        }
        __syncthreads();
    }
    #pragma unroll
    for (int r = 0; r < 4; r++)
        #pragma unroll
        for (int c = 0; c < 4; c++)
            C[(size_t)(m0 + ty*4 + r)*ldc + n0 + tx*4 + c] = acc[r][c];
}

// ---------------- s/d attention coefficients ----------------
__global__ void sd_kernel(const float* __restrict__ h,
                          const float* __restrict__ a_src,
                          const float* __restrict__ a_dst,
                          float* __restrict__ s_out, float* __restrict__ d_out,
                          int F, int Hh, int D) {
    int row = blockIdx.x;    // b*EE + e
    int t = threadIdx.x;     // F threads
    float v = h[(size_t)row*F + t];
    __shared__ float ss[256], sd2[256];
    ss[t] = v * a_src[t];
    sd2[t] = v * a_dst[t];
    __syncthreads();
    int dd = t % D;
    for (int st = D >> 1; st > 0; st >>= 1) {
        if (dd < st) { ss[t] += ss[t+st]; sd2[t] += sd2[t+st]; }
        __syncthreads();
    }
    if (dd == 0) {
        int head = t / D;
        int b = row >> 7, e = row & 127;
        int o = (b*Hh + head)*EE + e;
        s_out[o] = ss[t];
        d_out[o] = sd2[t];
    }
}

// ---------------- attention softmax rows (alpha) ----------------
__global__ void alpha_kernel(const float* __restrict__ s,
                             const float* __restrict__ d,
                             float* __restrict__ alpha) {
    int g = (blockIdx.x * blockDim.x + threadIdx.x) >> 5;   // global warp id
    int lane = threadIdx.x & 31;
    int bh = g / EE, i = g % EE;
    float di = d[bh*EE + i];
    float ev[4]; float m = -1e30f;
    #pragma unroll
    for (int q = 0; q < 4; q++) {
        int j = lane + q*32;
        float e = di + s[bh*EE + j];
        e = (e >= 0.f) ? e : 0.2f*e;       // leaky_relu(0.2)
        ev[q] = e;
        m = fmaxf(m, e);
    }
    #pragma unroll
    for (int off = 16; off > 0; off >>= 1) m = fmaxf(m, __shfl_xor_sync(0xffffffffu, m, off));
    float sum = 0.f;
    #pragma unroll
    for (int q = 0; q < 4; q++) { ev[q] = __expf(ev[q] - m); sum += ev[q]; }
    #pragma unroll
    for (int off = 16; off > 0; off >>= 1) sum += __shfl_xor_sync(0xffffffffu, sum, off);
    float inv = 1.f / sum;
    #pragma unroll
    for (int q = 0; q < 4; q++)
        alpha[(size_t)(bh*EE + i)*EE + lane + q*32] = ev[q]*inv;
}

// ---------------- bias + layernorm + elu ----------------
__global__ void lnelu_kernel(const float* __restrict__ in,
                             const float* __restrict__ bias,
                             const float* __restrict__ g,
                             const float* __restrict__ bt,
                             float* __restrict__ out, int F) {
    int row = blockIdx.x;
    int t = threadIdx.x;          // F threads
    float v = in[(size_t)row*F + t] + bias[t];
    float s = v, s2 = v*v;
    #pragma unroll
    for (int off = 16; off > 0; off >>= 1) {
        s  += __shfl_xor_sync(0xffffffffu, s,  off);
        s2 += __shfl_xor_sync(0xffffffffu, s2, off);
    }
    __shared__ float ws[8], ws2[8];
    int wid = t >> 5, lane = t & 31, nw = F >> 5;
    if (lane == 0) { ws[wid] = s; ws2[wid] = s2; }
    __syncthreads();
    float S = 0.f, S2 = 0.f;
    for (int k = 0; k < nw; k++) { S += ws[k]; S2 += ws2[k]; }
    float mean = S / F;
    float var = S2 / F - mean*mean;
    float y = (v - mean) * rsqrtf(var + 1e-5f) * g[t] + bt[t];
    out[(size_t)row*F + t] = (y > 0.f) ? y : expm1f(y);
}

// ---------------- cls projection (per batch) ----------------
__global__ void clsproj_kernel(const float* __restrict__ seq,
                               const float* __restrict__ Wr1,
                               float* __restrict__ out) {
    int b = blockIdx.x;
    int c = threadIdx.x;  // 256
    __shared__ float cls[HH];
    for (int h = c; h < HH; h += 256) cls[h] = seq[(size_t)b*SS*HH + h];
    __syncthreads();
    float acc = 0.f;
    const float* w = Wr1 + (size_t)160*256 + c;
    for (int h = 0; h < HH; h++) acc += cls[h] * w[(size_t)h*256];
    out[b*256 + c] = acc;
}

// ---------------- relation-type projection ----------------
__global__ void relproj_kernel(const float* __restrict__ remb,
                               const float* __restrict__ Wr1,
                               float* __restrict__ out) {
    int r = blockIdx.x;
    int c = threadIdx.x;
    __shared__ float rv[RDD];
    if (c < RDD) rv[c] = remb[r*RDD + c];
    __syncthreads();
    float acc = 0.f;
    #pragma unroll
    for (int k = 0; k < RDD; k++) acc += rv[k] * Wr1[(size_t)(128 + k)*256 + c];
    out[r*256 + c] = acc;
}

// ---------------- final pair scores ----------------
__global__ void pair_kernel(const int* __restrict__ pidx,
                            const int* __restrict__ rids,
                            const float* __restrict__ p1,
                            const float* __restrict__ p2,
                            const float* __restrict__ relp,
                            const float* __restrict__ clsp,
                            const float* __restrict__ br1,
                            const float* __restrict__ Wr2,
                            const float* __restrict__ br2,
                            float* __restrict__ out) {
    int g = (blockIdx.x * blockDim.x + threadIdx.x) >> 5;   // pair id
    int lane = threadIdx.x & 31;
    int b = g / PP, p = g % PP;
    int pi = pidx[(b*PP + p)*2 + 0];
    int pj = pidx[(b*PP + p)*2 + 1];
    int r  = rids[b*PP + p];
    const float* a1 = p1 + (size_t)(b*EE + pi)*256;
    const float* a2 = p2 + (size_t)(b*EE + pj)*256;
    const float* ar = relp + r*256;
    const float* ac = clsp + b*256;
    float acc = 0.f;
    #pragma unroll
    for (int q = 0; q < 8; q++) {
        int c = lane + q*32;
        float v = a1[c] + a2[c] + ar[c] + ac[c] + br1[c];
        v = fmaxf(v, 0.f);
        acc += v * Wr2[c];
    }
    #pragma unroll
    for (int off = 16; off > 0; off >>= 1) acc += __shfl_xor_sync(0xffffffffu, acc, off);
    if (lane == 0) out[b*PP + p] = acc + br2[0];
}

// ---------------- launch ----------------
extern "C" void kernel_launch(void* const* d_in, const int* in_sizes, int n_in,
                              void* d_out, int out_size) {
    const float* seq      = (const float*)d_in[0];
    const int*   starts   = (const int*)  d_in[1];
    const int*   type_ids = (const int*)  d_in[2];
    const int*   pair_idx = (const int*)  d_in[3];
    const int*   rel_ids  = (const int*)  d_in[4];
    const float* temb     = (const float*)d_in[5];
    const float* remb     = (const float*)d_in[6];
    const float* W1       = (const float*)d_in[7];
    const float* a_src1   = (const float*)d_in[8];
    const float* a_dst1   = (const float*)d_in[9];
    const float* b1       = (const float*)d_in[10];
    const float* ln1_g    = (const float*)d_in[11];
    const float* ln1_b    = (const float*)d_in[12];
    const float* W2       = (const float*)d_in[13];
    const float* a_src2   = (const float*)d_in[14];
    const float* a_dst2   = (const float*)d_in[15];
    const float* b2       = (const float*)d_in[16];
    const float* ln2_g    = (const float*)d_in[17];
    const float* ln2_b    = (const float*)d_in[18];
    const float* Wr1      = (const float*)d_in[19];
    const float* br1      = (const float*)d_in[20];
    const float* Wr2      = (const float*)d_in[21];
    const float* br2      = (const float*)d_in[22];
    float* out = (float*)d_out;

    float *x0, *h1, *s1, *d1, *al1, *o1, *x1, *h2, *s2, *d2, *al2, *o2, *x2;
    float *p1, *p2, *clsp, *relp;
    cudaGetSymbolAddress((void**)&x0,  g_x0);
    cudaGetSymbolAddress((void**)&h1,  g_h1);
    cudaGetSymbolAddress((void**)&s1,  g_s1);
    cudaGetSymbolAddress((void**)&d1,  g_d1);
    cudaGetSymbolAddress((void**)&al1, g_alpha1);
    cudaGetSymbolAddress((void**)&o1,  g_o1);
    cudaGetSymbolAddress((void**)&x1,  g_x1);
    cudaGetSymbolAddress((void**)&h2,  g_h2);
    cudaGetSymbolAddress((void**)&s2,  g_s2);
    cudaGetSymbolAddress((void**)&d2,  g_d2);
    cudaGetSymbolAddress((void**)&al2, g_alpha2);
    cudaGetSymbolAddress((void**)&o2,  g_o2);
    cudaGetSymbolAddress((void**)&x2,  g_x2);
    cudaGetSymbolAddress((void**)&p1,  g_p1);
    cudaGetSymbolAddress((void**)&p2,  g_p2);
    cudaGetSymbolAddress((void**)&clsp, g_cls);
    cudaGetSymbolAddress((void**)&relp, g_rel);

    // 1. pooling + type emb
    pool_kernel<<<BB*EE, 256>>>(seq, starts, type_ids, temb, x0);

    // 2. h1 = x0 @ W1  (4096,768)@(768,256)
    gemm_kernel<<<dim3(4, 64, 1), 256>>>(x0, W1, h1, BB*EE, F1, HH,
                                         HH, F1, F1, 1, 0, 0, 0, 0, 0);

    // 3. s1,d1
    sd_kernel<<<BB*EE, F1>>>(h1, a_src1, a_dst1, s1, d1, F1, HEADS1, DD1);

    // 4. alpha1 (B*2*E rows)
    alpha_kernel<<<(BB*HEADS1*EE)/4, 128>>>(s1, d1, al1);

    // 5. o1 = alpha1 @ h1 per (b,head)
    gemm_kernel<<<dim3(2, 2, BB*HEADS1), 256>>>(al1, h1, o1, EE, DD1, EE,
                                                EE, F1, F1, HEADS1,
                                                (long)EE*EE, (long)EE*F1, DD1,
                                                (long)EE*F1, DD1);

    // 6. x1 = elu(ln(o1 + b1))
    lnelu_kernel<<<BB*EE, F1>>>(o1, b1, ln1_g, ln1_b, x1, F1);

    // 7. h2 = x1 @ W2  (4096,256)@(256,64)
    gemm_kernel<<<dim3(1, 64, 1), 256>>>(x1, W2, h2, BB*EE, DD2, F1,
                                         F1, DD2, DD2, 1, 0, 0, 0, 0, 0);

    // 8. s2,d2
    sd_kernel<<<BB*EE, DD2>>>(h2, a_src2, a_dst2, s2, d2, DD2, 1, DD2);

    // 9. alpha2
    alpha_kernel<<<(BB*EE)/4, 128>>>(s2, d2, al2);

    // 10. o2 = alpha2 @ h2 per b
    gemm_kernel<<<dim3(1, 2, BB), 256>>>(al2, h2, o2, EE, DD2, EE,
                                         EE, DD2, DD2, 1,
                                         (long)EE*EE, (long)EE*DD2, 0,
                                         (long)EE*DD2, 0);

    // 11. x2 = elu(ln(o2 + b2))
    lnelu_kernel<<<BB*EE, DD2>>>(o2, b2, ln2_g, ln2_b, x2, DD2);

    // 12/13. pair projections p1 = x2 @ Wr1[0:64], p2 = x2 @ Wr1[64:128]
    gemm_kernel<<<dim3(4, 64, 1), 256>>>(x2, Wr1, p1, BB*EE, 256, DD2,
                                         DD2, 256, 256, 1, 0, 0, 0, 0, 0);
    gemm_kernel<<<dim3(4, 64, 1), 256>>>(x2, Wr1 + (size_t)64*256, p2, BB*EE, 256, DD2,
                                         DD2, 256, 256, 1, 0, 0, 0, 0, 0);

    // 14. cls projection
    clsproj_kernel<<<BB, 256>>>(seq, Wr1, clsp);

    // 15. relation-type projection
    relproj_kernel<<<NRR, 256>>>(remb, Wr1, relp);

    // 16. pair scores
    pair_kernel<<<(BB*PP)/8, 256>>>(pair_idx, rel_ids, p1, p2, relp, clsp,
                                    br1, Wr2, br2, out);
}

// round 2
// speedup vs baseline: 1.2042x; 1.2042x over previous
#include <cuda_runtime.h>
#include <cuda_bf16.h>
#include <math.h>
#include <stdint.h>

#define BB 32
#define SS 1024
#define HH 768
#define EE 128
#define WW 8
#define PP 512
#define NTT 5
#define NRR 9
#define DD1 128
#define HEADS1 2
#define DD2 64
#define RDD 32
#define F1 256  // HEADS1*DD1

// ---------------- scratch (device globals, no allocation) ----------------
static __device__ float g_x0[BB*EE*HH];
static __device__ float g_h1[BB*EE*F1];
static __device__ float g_s1[BB*HEADS1*EE];
static __device__ float g_d1[BB*HEADS1*EE];
static __device__ float g_alpha1[BB*HEADS1*EE*EE];
static __device__ float g_o1[BB*EE*F1];
static __device__ float g_x1[BB*EE*F1];
static __device__ float g_h2[BB*EE*DD2];
static __device__ float g_s2[BB*EE];
static __device__ float g_d2[BB*EE];
static __device__ float g_alpha2[BB*EE*EE];
static __device__ float g_o2[BB*EE*DD2];
static __device__ float g_x2[BB*EE*DD2];
static __device__ float g_p1[BB*EE*256];
static __device__ float g_p2[BB*EE*256];
static __device__ float g_cls[BB*256];
static __device__ float g_rel[NRR*256];

// ---------------- 1. entity pooling + type embedding ----------------
__global__ void pool_kernel(const float* __restrict__ seq,
                            const int* __restrict__ starts,
                            const int* __restrict__ type_ids,
                            const float* __restrict__ temb,
                            float* __restrict__ x0) {
    int be = blockIdx.x;
    int b = be >> 7;
    int t = threadIdx.x;                 // 256 threads
    __shared__ float toks[WW*HH];
    __shared__ float colsum[HH];
    __shared__ float logits[WW];

    int start = starts[be];
    const float* base = seq + ((size_t)b*SS + start)*HH;
    for (int i = t; i < WW*HH; i += 256) toks[i] = base[i];
    __syncthreads();

    for (int h = t; h < HH; h += 256) {
        float cs = 0.f;
        #pragma unroll
        for (int w = 0; w < WW; w++) cs += toks[w*HH + h];
        colsum[h] = cs;
    }
    __syncthreads();

    int warp = t >> 5, lane = t & 31;
    {
        float acc = 0.f;
        for (int h = lane; h < HH; h += 32) acc += toks[warp*HH + h] * colsum[h];
        #pragma unroll
        for (int off = 16; off > 0; off >>= 1) acc += __shfl_xor_sync(0xffffffffu, acc, off);
        if (lane == 0) logits[warp] = acc * 0.125f;
    }
    __syncthreads();

    float m = logits[0];
    #pragma unroll
    for (int w = 1; w < WW; w++) m = fmaxf(m, logits[w]);
    float ex[WW]; float sum = 0.f;
    #pragma unroll
    for (int w = 0; w < WW; w++) { ex[w] = __expf(logits[w] - m); sum += ex[w]; }
    float inv = 1.f / sum;

    int type = type_ids[be];
    const float* te = temb + (size_t)type*HH;
    for (int h = t; h < HH; h += 256) {
        float p = 0.f;
        #pragma unroll
        for (int w = 0; w < WW; w++) p += ex[w] * toks[w*HH + h];
        x0[(size_t)be*HH + h] = p*inv + te[h];
    }
}

// ---------------- tf32x3 tensor-core GEMM ----------------
// C[M,N] = A[M,K] @ B[K,N], fp32 in/out, tf32x3 compensated (rel err ~2^-22).
// Block tile 64x64, K-chunk 32. 8 warps as 2(m) x 4(n); warp tile 32x16.
// Batched via blockIdx.z: bb = z/Hh, hh = z%Hh.
__device__ __forceinline__ void mma8(float* d, const uint32_t* a, const uint32_t* b) {
    asm volatile(
        "mma.sync.aligned.m16n8k8.row.col.f32.tf32.tf32.f32 "
        "{%0,%1,%2,%3},{%4,%5,%6,%7},{%8,%9},{%0,%1,%2,%3};"
        : "+f"(d[0]), "+f"(d[1]), "+f"(d[2]), "+f"(d[3])
        : "r"(a[0]), "r"(a[1]), "r"(a[2]), "r"(a[3]), "r"(b[0]), "r"(b[1]));
}
__device__ __forceinline__ void split_tf32(float v, uint32_t& hi, uint32_t& lo) {
    asm("cvt.rna.tf32.f32 %0, %1;" : "=r"(hi) : "f"(v));
    float hf = __uint_as_float(hi);
    asm("cvt.rna.tf32.f32 %0, %1;" : "=r"(lo) : "f"(v - hf));
}

#define SA 36   // A smem stride (banks: 4g+ti -> conflict-free frag loads)
#define SB 72   // B smem stride (banks: 8ti+g -> conflict-free frag loads)

__global__ __launch_bounds__(256) void tf32_gemm(
        const float* __restrict__ A, const float* __restrict__ Bm,
        float* __restrict__ C,
        int M, int N, int K, int lda, int ldb, int ldc,
        int Hh, long sA, long sBb, long sBh, long sCb, long sCh) {
    int bz = blockIdx.z;
    int bb = bz / Hh, hh = bz - bb*Hh;
    A  += (long)bz * sA;
    Bm += (long)bb * sBb + (long)hh * sBh;
    C  += (long)bb * sCb + (long)hh * sCh;

    __shared__ uint32_t AsH[64][SA], AsL[64][SA];
    __shared__ uint32_t BsH[32][SB], BsL[32][SB];

    int tid = threadIdx.x;
    int wid = tid >> 5, lane = tid & 31;
    int g = lane >> 2, ti = lane & 3;
    int warp_m = wid >> 2;          // 0..1 -> 32 rows
    int warp_n = wid & 3;           // 0..3 -> 16 cols
    int m0 = blockIdx.y * 64, n0 = blockIdx.x * 64;

    float acc[2][2][4] = {};

    for (int kc = 0; kc < K; kc += 32) {
        // load + split A chunk (64 x 32)
        #pragma unroll
        for (int i = 0; i < 2; i++) {
            int idx = tid + i*256;
            int row = idx >> 3, c4 = (idx & 7) * 4;
            float4 av = *(const float4*)(A + (size_t)(m0 + row)*lda + kc + c4);
            uint4 h4, l4;
            split_tf32(av.x, h4.x, l4.x); split_tf32(av.y, h4.y, l4.y);
            split_tf32(av.z, h4.z, l4.z); split_tf32(av.w, h4.w, l4.w);
            *(uint4*)&AsH[row][c4] = h4;
            *(uint4*)&AsL[row][c4] = l4;
        }
        // load + split B chunk (32 x 64)
        #pragma unroll
        for (int i = 0; i < 2; i++) {
            int idx = tid + i*256;
            int row = idx >> 4, c4 = (idx & 15) * 4;
            float4 bv = *(const float4*)(Bm + (size_t)(kc + row)*ldb + n0 + c4);
            uint4 h4, l4;
            split_tf32(bv.x, h4.x, l4.x); split_tf32(bv.y, h4.y, l4.y);
            split_tf32(bv.z, h4.z, l4.z); split_tf32(bv.w, h4.w, l4.w);
            *(uint4*)&BsH[row][c4] = h4;
            *(uint4*)&BsL[row][c4] = l4;
        }
        __syncthreads();

        #pragma unroll
        for (int ks = 0; ks < 4; ks++) {
            int k0 = ks * 8;
            uint32_t aH[2][4], aL[2][4], bH[2][2], bL[2][2];
            #pragma unroll
            for (int mt = 0; mt < 2; mt++) {
                int rm = warp_m*32 + mt*16;
                aH[mt][0] = AsH[rm + g    ][k0 + ti    ];
                aH[mt][1] = AsH[rm + g + 8][k0 + ti    ];
                aH[mt][2] = AsH[rm + g    ][k0 + ti + 4];
                aH[mt][3] = AsH[rm + g + 8][k0 + ti + 4];
                aL[mt][0] = AsL[rm + g    ][k0 + ti    ];
                aL[mt][1] = AsL[rm + g + 8][k0 + ti    ];
                aL[mt][2] = AsL[rm + g    ][k0 + ti + 4];
                aL[mt][3] = AsL[rm + g + 8][k0 + ti + 4];
            }
            #pragma unroll
            for (int nt = 0; nt < 2; nt++) {
                int cn = warp_n*16 + nt*8;
                bH[nt][0] = BsH[k0 + ti    ][cn + g];
                bH[nt][1] = BsH[k0 + ti + 4][cn + g];
                bL[nt][0] = BsL[k0 + ti    ][cn + g];
                bL[nt][1] = BsL[k0 + ti + 4][cn + g];
            }
            #pragma unroll
            for (int mt = 0; mt < 2; mt++)
                #pragma unroll
                for (int nt = 0; nt < 2; nt++) {
                    mma8(acc[mt][nt], aH[mt], bL[nt]);
                    mma8(acc[mt][nt], aL[mt], bH[nt]);
                    mma8(acc[mt][nt], aH[mt], bH[nt]);
                }
        }
        __syncthreads();
    }

    // epilogue
    #pragma unroll
    for (int mt = 0; mt < 2; mt++) {
        int rm = m0 + warp_m*32 + mt*16;
        #pragma unroll
        for (int nt = 0; nt < 2; nt++) {
            int cn = n0 + warp_n*16 + nt*8;
            float* c0 = C + (size_t)(rm + g)*ldc + cn + 2*ti;
            float* c2 = C + (size_t)(rm + g + 8)*ldc + cn + 2*ti;
            c0[0] = acc[mt][nt][0]; c0[1] = acc[mt][nt][1];
            c2[0] = acc[mt][nt][2]; c2[1] = acc[mt][nt][3];
        }
    }
}

// ---------------- s/d attention coefficients ----------------
__global__ void sd_kernel(const float* __restrict__ h,
                          const float* __restrict__ a_src,
                          const float* __restrict__ a_dst,
                          float* __restrict__ s_out, float* __restrict__ d_out,
                          int F, int Hh, int D) {
    int row = blockIdx.x;
    int t = threadIdx.x;
    float v = h[(size_t)row*F + t];
    __shared__ float ss[256], sd2[256];
    ss[t] = v * a_src[t];
    sd2[t] = v * a_dst[t];
    __syncthreads();
    int dd = t % D;
    for (int st = D >> 1; st > 0; st >>= 1) {
        if (dd < st) { ss[t] += ss[t+st]; sd2[t] += sd2[t+st]; }
        __syncthreads();
    }
    if (dd == 0) {
        int head = t / D;
        int b = row >> 7, e = row & 127;
        int o = (b*Hh + head)*EE + e;
        s_out[o] = ss[t];
        d_out[o] = sd2[t];
    }
}

// ---------------- attention softmax rows (alpha) ----------------
__global__ void alpha_kernel(const float* __restrict__ s,
                             const float* __restrict__ d,
                             float* __restrict__ alpha) {
    int g = (blockIdx.x * blockDim.x + threadIdx.x) >> 5;
    int lane = threadIdx.x & 31;
    int bh = g / EE, i = g % EE;
    float di = d[bh*EE + i];
    float ev[4]; float m = -1e30f;
    #pragma unroll
    for (int q = 0; q < 4; q++) {
        int j = lane + q*32;
        float e = di + s[bh*EE + j];
        e = (e >= 0.f) ? e : 0.2f*e;
        ev[q] = e;
        m = fmaxf(m, e);
    }
    #pragma unroll
    for (int off = 16; off > 0; off >>= 1) m = fmaxf(m, __shfl_xor_sync(0xffffffffu, m, off));
    float sum = 0.f;
    #pragma unroll
    for (int q = 0; q < 4; q++) { ev[q] = __expf(ev[q] - m); sum += ev[q]; }
    #pragma unroll
    for (int off = 16; off > 0; off >>= 1) sum += __shfl_xor_sync(0xffffffffu, sum, off);
    float inv = 1.f / sum;
    #pragma unroll
    for (int q = 0; q < 4; q++)
        alpha[(size_t)(bh*EE + i)*EE + lane + q*32] = ev[q]*inv;
}

// ---------------- bias + layernorm + elu ----------------
__global__ void lnelu_kernel(const float* __restrict__ in,
                             const float* __restrict__ bias,
                             const float* __restrict__ g,
                             const float* __restrict__ bt,
                             float* __restrict__ out, int F) {
    int row = blockIdx.x;
    int t = threadIdx.x;
    float v = in[(size_t)row*F + t] + bias[t];
    float s = v, s2 = v*v;
    #pragma unroll
    for (int off = 16; off > 0; off >>= 1) {
        s  += __shfl_xor_sync(0xffffffffu, s,  off);
        s2 += __shfl_xor_sync(0xffffffffu, s2, off);
    }
    __shared__ float ws[8], ws2[8];
    int wid = t >> 5, lane = t & 31, nw = F >> 5;
    if (lane == 0) { ws[wid] = s; ws2[wid] = s2; }
    __syncthreads();
    float S = 0.f, S2 = 0.f;
    for (int k = 0; k < nw; k++) { S += ws[k]; S2 += ws2[k]; }
    float mean = S / F;
    float var = S2 / F - mean*mean;
    float y = (v - mean) * rsqrtf(var + 1e-5f) * g[t] + bt[t];
    out[(size_t)row*F + t] = (y > 0.f) ? y : expm1f(y);
}

// ---------------- cls projection (per batch), br1 folded in ----------------
__global__ void clsproj_kernel(const float* __restrict__ seq,
                               const float* __restrict__ Wr1,
                               const float* __restrict__ br1,
                               float* __restrict__ out) {
    int b = blockIdx.x;
    int c = threadIdx.x;  // 256
    __shared__ float cls[HH];
    for (int h = c; h < HH; h += 256) cls[h] = seq[(size_t)b*SS*HH + h];
    __syncthreads();
    float acc = br1[c];
    const float* w = Wr1 + (size_t)160*256 + c;
    for (int h = 0; h < HH; h++) acc += cls[h] * w[(size_t)h*256];
    out[b*256 + c] = acc;
}

// ---------------- relation-type projection ----------------
__global__ void relproj_kernel(const float* __restrict__ remb,
                               const float* __restrict__ Wr1,
                               float* __restrict__ out) {
    int r = blockIdx.x;
    int c = threadIdx.x;
    __shared__ float rv[RDD];
    if (c < RDD) rv[c] = remb[r*RDD + c];
    __syncthreads();
    float acc = 0.f;
    #pragma unroll
    for (int k = 0; k < RDD; k++) acc += rv[k] * Wr1[(size_t)(128 + k)*256 + c];
    out[r*256 + c] = acc;
}

// ---------------- final pair scores ----------------
__global__ void pair_kernel(const int* __restrict__ pidx,
                            const int* __restrict__ rids,
                            const float* __restrict__ p1,
                            const float* __restrict__ p2,
                            const float* __restrict__ relp,
                            const float* __restrict__ clsp,
                            const float* __restrict__ Wr2,
                            const float* __restrict__ br2,
                            float* __restrict__ out) {
    int g = (blockIdx.x * blockDim.x + threadIdx.x) >> 5;
    int lane = threadIdx.x & 31;
    int b = g / PP, p = g % PP;
    int pi = pidx[(b*PP + p)*2 + 0];
    int pj = pidx[(b*PP + p)*2 + 1];
    int r  = rids[b*PP + p];
    const float* a1 = p1 + (size_t)(b*EE + pi)*256;
    const float* a2 = p2 + (size_t)(b*EE + pj)*256;
    const float* ar = relp + r*256;
    const float* ac = clsp + b*256;
    float acc = 0.f;
    #pragma unroll
    for (int q = 0; q < 8; q++) {
        int c = lane + q*32;
        float v = a1[c] + a2[c] + ar[c] + ac[c];
        v = fmaxf(v, 0.f);
        acc += v * Wr2[c];
    }
    #pragma unroll
    for (int off = 16; off > 0; off >>= 1) acc += __shfl_xor_sync(0xffffffffu, acc, off);
    if (lane == 0) out[b*PP + p] = acc + br2[0];
}

// ---------------- launch ----------------
extern "C" void kernel_launch(void* const* d_in, const int* in_sizes, int n_in,
                              void* d_out, int out_size) {
    const float* seq      = (const float*)d_in[0];
    const int*   starts   = (const int*)  d_in[1];
    const int*   type_ids = (const int*)  d_in[2];
    const int*   pair_idx = (const int*)  d_in[3];
    const int*   rel_ids  = (const int*)  d_in[4];
    const float* temb     = (const float*)d_in[5];
    const float* remb     = (const float*)d_in[6];
    const float* W1       = (const float*)d_in[7];
    const float* a_src1   = (const float*)d_in[8];
    const float* a_dst1   = (const float*)d_in[9];
    const float* b1       = (const float*)d_in[10];
    const float* ln1_g    = (const float*)d_in[11];
    const float* ln1_b    = (const float*)d_in[12];
    const float* W2       = (const float*)d_in[13];
    const float* a_src2   = (const float*)d_in[14];
    const float* a_dst2   = (const float*)d_in[15];
    const float* b2       = (const float*)d_in[16];
    const float* ln2_g    = (const float*)d_in[17];
    const float* ln2_b    = (const float*)d_in[18];
    const float* Wr1      = (const float*)d_in[19];
    const float* br1      = (const float*)d_in[20];
    const float* Wr2      = (const float*)d_in[21];
    const float* br2      = (const float*)d_in[22];
    float* out = (float*)d_out;

    float *x0, *h1, *s1, *d1, *al1, *o1, *x1, *h2, *s2, *d2, *al2, *o2, *x2;
    float *p1, *p2, *clsp, *relp;
    cudaGetSymbolAddress((void**)&x0,  g_x0);
    cudaGetSymbolAddress((void**)&h1,  g_h1);
    cudaGetSymbolAddress((void**)&s1,  g_s1);
    cudaGetSymbolAddress((void**)&d1,  g_d1);
    cudaGetSymbolAddress((void**)&al1, g_alpha1);
    cudaGetSymbolAddress((void**)&o1,  g_o1);
    cudaGetSymbolAddress((void**)&x1,  g_x1);
    cudaGetSymbolAddress((void**)&h2,  g_h2);
    cudaGetSymbolAddress((void**)&s2,  g_s2);
    cudaGetSymbolAddress((void**)&d2,  g_d2);
    cudaGetSymbolAddress((void**)&al2, g_alpha2);
    cudaGetSymbolAddress((void**)&o2,  g_o2);
    cudaGetSymbolAddress((void**)&x2,  g_x2);
    cudaGetSymbolAddress((void**)&p1,  g_p1);
    cudaGetSymbolAddress((void**)&p2,  g_p2);
    cudaGetSymbolAddress((void**)&clsp, g_cls);
    cudaGetSymbolAddress((void**)&relp, g_rel);

    // 1. pooling + type emb
    pool_kernel<<<BB*EE, 256>>>(seq, starts, type_ids, temb, x0);

    // 2. h1 = x0 @ W1  (4096,768)@(768,256)
    tf32_gemm<<<dim3(4, 64, 1), 256>>>(x0, W1, h1, BB*EE, F1, HH,
                                       HH, F1, F1, 1, 0, 0, 0, 0, 0);

    // 3. s1,d1
    sd_kernel<<<BB*EE, F1>>>(h1, a_src1, a_dst1, s1, d1, F1, HEADS1, DD1);

    // 4. alpha1
    alpha_kernel<<<(BB*HEADS1*EE)/4, 128>>>(s1, d1, al1);

    // 5. o1 = alpha1 @ h1 per (b,head): M=128 N=128 K=128
    tf32_gemm<<<dim3(2, 2, BB*HEADS1), 256>>>(al1, h1, o1, EE, DD1, EE,
                                              EE, F1, F1, HEADS1,
                                              (long)EE*EE, (long)EE*F1, DD1,
                                              (long)EE*F1, DD1);

    // 6. x1 = elu(ln(o1 + b1))
    lnelu_kernel<<<BB*EE, F1>>>(o1, b1, ln1_g, ln1_b, x1, F1);

    // 7. h2 = x1 @ W2  (4096,256)@(256,64)
    tf32_gemm<<<dim3(1, 64, 1), 256>>>(x1, W2, h2, BB*EE, DD2, F1,
                                       F1, DD2, DD2, 1, 0, 0, 0, 0, 0);

    // 8. s2,d2
    sd_kernel<<<BB*EE, DD2>>>(h2, a_src2, a_dst2, s2, d2, DD2, 1, DD2);

    // 9. alpha2
    alpha_kernel<<<(BB*EE)/4, 128>>>(s2, d2, al2);

    // 10. o2 = alpha2 @ h2 per b: M=128 N=64 K=128
    tf32_gemm<<<dim3(1, 2, BB), 256>>>(al2, h2, o2, EE, DD2, EE,
                                       EE, DD2, DD2, 1,
                                       (long)EE*EE, (long)EE*DD2, 0,
                                       (long)EE*DD2, 0);

    // 11. x2 = elu(ln(o2 + b2))
    lnelu_kernel<<<BB*EE, DD2>>>(o2, b2, ln2_g, ln2_b, x2, DD2);

    // 12/13. pair projections
    tf32_gemm<<<dim3(4, 64, 1), 256>>>(x2, Wr1, p1, BB*EE, 256, DD2,
                                       DD2, 256, 256, 1, 0, 0, 0, 0, 0);
    tf32_gemm<<<dim3(4, 64, 1), 256>>>(x2, Wr1 + (size_t)64*256, p2, BB*EE, 256, DD2,
                                       DD2, 256, 256, 1, 0, 0, 0, 0, 0);

    // 14. cls projection (+br1)
    clsproj_kernel<<<BB, 256>>>(seq, Wr1, br1, clsp);

    // 15. relation-type projection
    relproj_kernel<<<NRR, 256>>>(remb, Wr1, relp);

    // 16. pair scores
    pair_kernel<<<(BB*PP)/8, 256>>>(pair_idx, rel_ids, p1, p2, relp, clsp,
                                    Wr2, br2, out);
}